// round 8
// baseline (speedup 1.0000x reference)
#include <cuda_runtime.h>

#define NBLK 296
#define NTHR 1024
#define NWARP (NBLK*32)     // 9472
#define NT (NBLK*NTHR)      // 303104

#define Bn 4
#define Cn 256
#define ICn 128
#define Sn 64
#define NTOK (Bn*Sn)        // 256
#define REGION 1024
#define EPSf 1e-5f

// Scratch (allocation-free __device__ globals)
__device__ float d_P   [NTOK*Cn];      // pooled tokens [tok][c]
__device__ float d_g   [NTOK*ICn];
__device__ float d_th  [NTOK*ICn];
__device__ float d_ph  [NTOK*ICn];
__device__ float d_attn[NTOK*Sn];      // softmax rows
__device__ float d_y   [NTOK*ICn];     // [bs][i]
__device__ float d_Wt  [ICn*Cn];       // BN-folded W transposed [i][c]
__device__ float d_bias[Cn];
__device__ float d_valT[Bn*Sn*Cn];     // broadcast values TRANSPOSED [b][s][c]

// grid barrier (generation counter persists across graph replays)
__device__ unsigned g_cnt = 0;
__device__ unsigned g_gen = 0;

__device__ __forceinline__ void grid_sync() {
    __syncthreads();
    if (threadIdx.x == 0) {
        unsigned gen = *(volatile unsigned*)&g_gen;
        __threadfence();
        if (atomicAdd(&g_cnt, 1) == NBLK - 1) {
            g_cnt = 0;
            __threadfence();
            *(volatile unsigned*)&g_gen = gen + 1;
        } else {
            while (*(volatile unsigned*)&g_gen == gen) { }
        }
        __threadfence();
    }
    __syncthreads();
}

__global__ void __launch_bounds__(NTHR, 2) fused_kernel(
    const float* __restrict__ x,
    const float* __restrict__ g_w,  const float* __restrict__ g_b,
    const float* __restrict__ th_w, const float* __restrict__ th_b,
    const float* __restrict__ ph_w, const float* __restrict__ ph_b,
    const float* __restrict__ W_w,  const float* __restrict__ W_b,
    const float* __restrict__ gamma,const float* __restrict__ beta,
    const float* __restrict__ mean, const float* __restrict__ var,
    float* __restrict__ z)
{
    int tid  = threadIdx.x;
    int lane = tid & 31;
    int gw   = blockIdx.x * 32 + (tid >> 5);   // global warp id
    int gt   = blockIdx.x * NTHR + tid;        // global thread id

    // ---------------- Phase A: BN-fold of W + stripe mean pool ----------------
    if (gt < Cn * ICn) {                       // 32768 < NT: single shot
        int c = gt >> 7, i = gt & 127;
        float inv = gamma[c] * rsqrtf(var[c] + EPSf);
        d_Wt[i * Cn + c] = W_w[gt] * inv;
        if (gt < Cn) {
            float invc = gamma[gt] * rsqrtf(var[gt] + EPSf);
            d_bias[gt] = (W_b[gt] - mean[gt]) * invc + beta[gt];
        }
    }
    // pool: warp per 1024-float region r = (b*Cn+c)*Sn + s
    for (int r = gw; r < NTOK * Cn; r += NWARP) {
        const float4* p = (const float4*)(x + (size_t)r * REGION);
        float sum = 0.f;
#pragma unroll
        for (int i = 0; i < 8; i++) {
            float4 v = p[lane + i * 32];
            sum += (v.x + v.y) + (v.z + v.w);
        }
#pragma unroll
        for (int o = 16; o; o >>= 1) sum += __shfl_down_sync(0xffffffffu, sum, o);
        if (lane == 0) {
            int b = r >> 14;
            int rem = r & 16383;
            int c = rem >> 6, s = rem & 63;
            d_P[(b * Sn + s) * Cn + c] = sum * (1.0f / REGION);
        }
    }
    grid_sync();

    // ---------------- Phase B: g/theta/phi projections ----------------
    // warp tile: 2 tokens x 8 outputs; 128 token-tiles x 48 out-tiles = 6144 warps
    if (gw < 6144) {
        int tokT = gw & 127;
        int outT = gw >> 7;                  // 0..47
        int tok0 = tokT * 2;
        int o0   = outT * 8;                 // in [0,384)
        int m    = o0 >> 7;
        int i0   = o0 & 127;
        const float* wsrc = (m == 0) ? g_w : (m == 1) ? th_w : ph_w;
        const float* bsrc = (m == 0) ? g_b : (m == 1) ? th_b : ph_b;
        float*       osrc = (m == 0) ? d_g : (m == 1) ? d_th : d_ph;

        float acc[2][8];
#pragma unroll
        for (int t = 0; t < 2; t++)
#pragma unroll
            for (int j = 0; j < 8; j++) acc[t][j] = 0.f;

#pragma unroll
        for (int kk = 0; kk < 8; kk++) {
            int c = kk * 32 + lane;
            float pv0 = d_P[tok0 * Cn + c];
            float pv1 = d_P[(tok0 + 1) * Cn + c];
#pragma unroll
            for (int j = 0; j < 8; j++) {
                float wv = wsrc[(i0 + j) * Cn + c];
                acc[0][j] = fmaf(pv0, wv, acc[0][j]);
                acc[1][j] = fmaf(pv1, wv, acc[1][j]);
            }
        }
#pragma unroll
        for (int t = 0; t < 2; t++)
#pragma unroll
            for (int j = 0; j < 8; j++)
#pragma unroll
                for (int o = 16; o; o >>= 1)
                    acc[t][j] += __shfl_xor_sync(0xffffffffu, acc[t][j], o);

        if (lane < 16) {
            int mt = lane >> 3, mj = lane & 7;
            float outv = 0.f;
#pragma unroll
            for (int t = 0; t < 2; t++)
#pragma unroll
                for (int j = 0; j < 8; j++)
                    if (t == mt && j == mj) outv = acc[t][j];
            osrc[(tok0 + mt) * ICn + i0 + mj] = outv + bsrc[i0 + mj];
        }
    }
    grid_sync();

    // ---------------- Phase C: f row + softmax (warp per token row) ----------
    if (gw < NTOK) {
        int b = gw >> 6;
        float4 a = ((const float4*)(d_th + gw * ICn))[lane];
        float v0 = 0.f, v1 = 0.f;
#pragma unroll 4
        for (int r = 0; r < Sn; r++) {
            float4 p = ((const float4*)(d_ph + (b * Sn + r) * ICn))[lane];
            float acc = a.x * p.x + a.y * p.y + a.z * p.z + a.w * p.w;
#pragma unroll
            for (int o = 16; o; o >>= 1) acc += __shfl_xor_sync(0xffffffffu, acc, o);
            if (lane == (r & 31)) { if (r < 32) v0 = acc; else v1 = acc; }
        }
        float mx = fmaxf(v0, v1);
#pragma unroll
        for (int o = 16; o; o >>= 1) mx = fmaxf(mx, __shfl_xor_sync(0xffffffffu, mx, o));
        float e0 = __expf(v0 - mx), e1 = __expf(v1 - mx);
        float sum = e0 + e1;
#pragma unroll
        for (int o = 16; o; o >>= 1) sum += __shfl_xor_sync(0xffffffffu, sum, o);
        float inv = 1.0f / sum;
        d_attn[gw * Sn + lane]      = e0 * inv;
        d_attn[gw * Sn + lane + 32] = e1 * inv;
    }
    grid_sync();

    // ---------------- Phase D: y = attn @ g  (thread per (bs,i)) -------------
    if (gt < NTOK * ICn) {
        int bs = gt >> 7;
        int i  = gt & 127;
        int b  = bs >> 6;
        const float* arow = d_attn + bs * Sn;
        const float* gb   = d_g + (b * Sn) * ICn + i;
        float acc = 0.f;
#pragma unroll 8
        for (int r = 0; r < Sn; r++) acc = fmaf(arow[r], gb[r * ICn], acc);
        d_y[gt] = acc;
    }
    grid_sync();

    // ---------------- Phase E: valT[b][s][c] = Wt^T y + bias -----------------
    if (gt < Bn * Sn * Cn) {
        int c  = gt & 255;
        int bs = gt >> 8;                    // b*Sn + s
        const float* yr = d_y + bs * ICn;    // broadcast within group
        const float* wt = d_Wt + c;          // coalesced across c
        float acc = 0.f;
#pragma unroll 8
        for (int i = 0; i < ICn; i++)
            acc = fmaf(yr[i], wt[i * Cn], acc);
        d_valT[gt] = acc + d_bias[c];        // coalesced write
    }
    grid_sync();

    // ---------------- Phase F: broadcast + residual ----------------
    const int total4 = NTOK * Cn * (REGION / 4);   // 16,777,216 float4
    for (int idx = gt; idx < total4; idx += NT) {
        int r = idx >> 8;                    // region id: b[15:14] c[13:6] s[5:0]
        int vi = (r & 0xC000) | ((r & 0x3F) << 8) | ((r >> 6) & 0xFF);
        float v = d_valT[vi];
        float4 a = ((const float4*)x)[idx];
        a.x += v; a.y += v; a.z += v; a.w += v;
        ((float4*)z)[idx] = a;
    }
}

extern "C" void kernel_launch(void* const* d_in, const int* in_sizes, int n_in,
                              void* d_out, int out_size) {
    const float* x      = (const float*)d_in[0];
    const float* g_w    = (const float*)d_in[1];
    const float* g_b    = (const float*)d_in[2];
    const float* th_w   = (const float*)d_in[3];
    const float* th_b   = (const float*)d_in[4];
    const float* ph_w   = (const float*)d_in[5];
    const float* ph_b   = (const float*)d_in[6];
    const float* W_w    = (const float*)d_in[7];
    const float* W_b    = (const float*)d_in[8];
    const float* gamma  = (const float*)d_in[9];
    const float* beta   = (const float*)d_in[10];
    const float* mean   = (const float*)d_in[11];
    const float* var    = (const float*)d_in[12];
    float* z = (float*)d_out;

    fused_kernel<<<NBLK, NTHR>>>(x, g_w, g_b, th_w, th_b, ph_w, ph_b,
                                 W_w, W_b, gamma, beta, mean, var, z);
}

// round 9
// speedup vs baseline: 1.3122x; 1.3122x over previous
#include <cuda_runtime.h>

#define Bn 4
#define Cn 256
#define ICn 128
#define Sn 64
#define NTOK (Bn*Sn)        // 256
#define REGION 1024
#define EPSf 1e-5f

// Scratch (allocation-free __device__ globals)
__device__ float d_P   [NTOK*Cn];      // pooled tokens [tok][c]
__device__ float d_g   [NTOK*ICn];
__device__ float d_th  [NTOK*ICn];
__device__ float d_ph  [NTOK*ICn];
__device__ float d_Wt  [ICn*Cn];       // BN-folded W transposed: [i][c]
__device__ float d_bias[Cn];           // BN-folded bias
__device__ float d_val [Bn*Cn*Sn];     // broadcast values [b][c][s]

// ---------------------------------------------------------------------------
// K1: stripe mean pool. One warp per 1024-float contiguous region.
// x is single-use -> streaming loads (evict-first keeps L2 clean).
// ---------------------------------------------------------------------------
__global__ void pool_kernel(const float* __restrict__ x) {
    int warp = (blockIdx.x * blockDim.x + threadIdx.x) >> 5;   // 0..65535
    int lane = threadIdx.x & 31;
    const float4* p = (const float4*)(x + (size_t)warp * REGION);
    float sum = 0.f;
#pragma unroll
    for (int i = 0; i < 8; i++) {
        float4 v = __ldcs(p + lane + i * 32);
        sum += (v.x + v.y) + (v.z + v.w);
    }
#pragma unroll
    for (int o = 16; o; o >>= 1) sum += __shfl_down_sync(0xffffffffu, sum, o);
    if (lane == 0) {
        int b   = warp >> 14;
        int rem = warp & 16383;
        int c   = rem >> 6;
        int s   = rem & 63;
        d_P[(b * Sn + s) * Cn + c] = sum * (1.0f / REGION);
    }
}

// ---------------------------------------------------------------------------
// K2: g/theta/phi projections as one tiled GEMM (32x32 tiles).
// blockIdx.y == 12 slice additionally builds the BN-folded transposed W.
// ---------------------------------------------------------------------------
__global__ void proj_kernel(const float* __restrict__ g_w,  const float* __restrict__ g_b,
                            const float* __restrict__ th_w, const float* __restrict__ th_b,
                            const float* __restrict__ ph_w, const float* __restrict__ ph_b,
                            const float* __restrict__ W_w,  const float* __restrict__ W_b,
                            const float* __restrict__ gamma,const float* __restrict__ beta,
                            const float* __restrict__ mean, const float* __restrict__ var) {
    int oT = blockIdx.y;                 // 0..12
    int tid = threadIdx.x;

    if (oT == 12) {
        // BN fold + transpose: 8 blocks x 256 threads, 16 elems each
        int base = blockIdx.x * 4096;
#pragma unroll
        for (int l = 0; l < 16; l++) {
            int idx = base + l * 256 + tid;      // 0..32767 over [c][i]
            int c = idx >> 7, i = idx & 127;
            float inv = gamma[c] * rsqrtf(var[c] + EPSf);
            d_Wt[i * Cn + c] = W_w[idx] * inv;
        }
        if (blockIdx.x == 0) {
            int c = tid;
            float inv = gamma[c] * rsqrtf(var[c] + EPSf);
            d_bias[c] = (W_b[c] - mean[c]) * inv + beta[c];
        }
        return;
    }

    __shared__ float As[32][33];
    __shared__ float Bs[32][33];
    int t0 = blockIdx.x * 32;
    int mat  = oT >> 2;
    int row0 = (oT & 3) * 32;
    const float* wsrc = (mat == 0) ? g_w : (mat == 1) ? th_w : ph_w;
    const float* bsrc = (mat == 0) ? g_b : (mat == 1) ? th_b : ph_b;
    float*       osrc = (mat == 0) ? d_g : (mat == 1) ? d_th : d_ph;

    int tx = tid & 15, ty = tid >> 4;
    float acc[2][2] = {{0.f,0.f},{0.f,0.f}};

    for (int k0 = 0; k0 < Cn; k0 += 32) {
#pragma unroll
        for (int l = 0; l < 4; l++) {
            int idx = tid + l * 256;
            int r = idx >> 5, k = idx & 31;
            As[r][k] = d_P[(t0 + r) * Cn + k0 + k];
            Bs[r][k] = wsrc[(row0 + r) * Cn + k0 + k];
        }
        __syncthreads();
#pragma unroll
        for (int k = 0; k < 32; k++) {
            float a0 = As[ty * 2][k], a1 = As[ty * 2 + 1][k];
            float b0 = Bs[tx * 2][k], b1 = Bs[tx * 2 + 1][k];
            acc[0][0] = fmaf(a0, b0, acc[0][0]);
            acc[0][1] = fmaf(a0, b1, acc[0][1]);
            acc[1][0] = fmaf(a1, b0, acc[1][0]);
            acc[1][1] = fmaf(a1, b1, acc[1][1]);
        }
        __syncthreads();
    }
#pragma unroll
    for (int di = 0; di < 2; di++)
#pragma unroll
        for (int dj = 0; dj < 2; dj++) {
            int tok = t0 + ty * 2 + di;
            int i   = row0 + tx * 2 + dj;
            osrc[tok * ICn + i] = acc[di][dj] + bsrc[i];
        }
}

// ---------------------------------------------------------------------------
// K3: fused attention row + output projection + BN.
// One block per (b,s) token: f = th[s]·ph^T, softmax, y[s] = attn·g (smem),
// then val[b][:][s] = Wt^T · y[s] + bias  (coalesced over c).
// ---------------------------------------------------------------------------
__global__ void attn_kernel() {
    __shared__ float th_s[ICn];          // theta row
    __shared__ float at_s[Sn];           // f row -> attn row
    __shared__ float y_s[ICn];           // y row
    int bs = blockIdx.x;                 // b*Sn + s
    int b  = bs >> 6;
    int s  = bs & 63;
    int tid = threadIdx.x;
    int warp = tid >> 5, lane = tid & 31;

    if (tid < ICn) th_s[tid] = d_th[bs * ICn + tid];
    __syncthreads();

    // f[r] for r = warp*8 .. warp*8+7 (8 warps x 8 dots)
    const float4* th4 = (const float4*)th_s;
    float4 a = th4[lane];
#pragma unroll
    for (int d = 0; d < 8; d++) {
        int r = warp * 8 + d;
        float4 p = ((const float4*)(d_ph + (b * Sn + r) * ICn))[lane];
        float acc = a.x * p.x + a.y * p.y + a.z * p.z + a.w * p.w;
#pragma unroll
        for (int o = 16; o; o >>= 1) acc += __shfl_down_sync(0xffffffffu, acc, o);
        if (lane == 0) at_s[r] = acc;
    }
    __syncthreads();

    // softmax over 64 entries by warp 0
    if (warp == 0) {
        float v0 = at_s[lane], v1 = at_s[lane + 32];
        float m = fmaxf(v0, v1);
#pragma unroll
        for (int o = 16; o; o >>= 1) m = fmaxf(m, __shfl_xor_sync(0xffffffffu, m, o));
        float e0 = __expf(v0 - m), e1 = __expf(v1 - m);
        float sum = e0 + e1;
#pragma unroll
        for (int o = 16; o; o >>= 1) sum += __shfl_xor_sync(0xffffffffu, sum, o);
        float inv = 1.0f / sum;
        at_s[lane]      = e0 * inv;
        at_s[lane + 32] = e1 * inv;
    }
    __syncthreads();

    // y[i] = sum_r attn[r] * g[r][i] ; threads 0..127 each own an i
    if (tid < ICn) {
        const float* gb = d_g + b * Sn * ICn + tid;
        float acc = 0.f;
#pragma unroll 16
        for (int r = 0; r < Sn; r++) acc = fmaf(at_s[r], gb[r * ICn], acc);
        y_s[tid] = acc;
    }
    __syncthreads();

    // val[b][c][s] = sum_i Wt[i][c] * y[i] + bias[c]; thread = c (coalesced)
    {
        const float* wt = d_Wt + tid;    // stride Cn per i
        float acc = 0.f;
#pragma unroll 8
        for (int i = 0; i < ICn; i++)
            acc = fmaf(y_s[i], wt[i * Cn], acc);
        d_val[(b * Cn + tid) * Sn + s] = acc + d_bias[tid];
    }
}

// ---------------------------------------------------------------------------
// K4: broadcast + residual. Pure float4 stream with evict-first hints on the
// single-use x read and z write; d_val stays cached (heavy reuse).
// ---------------------------------------------------------------------------
__global__ void residual_kernel(const float* __restrict__ x, float* __restrict__ z) {
    int idx = blockIdx.x * blockDim.x + threadIdx.x;
    float v = d_val[idx >> 8];
    float4 a = __ldcs((const float4*)x + idx);
    a.x += v; a.y += v; a.z += v; a.w += v;
    __stcs((float4*)z + idx, a);
}

// ---------------------------------------------------------------------------
extern "C" void kernel_launch(void* const* d_in, const int* in_sizes, int n_in,
                              void* d_out, int out_size) {
    const float* x      = (const float*)d_in[0];
    const float* g_w    = (const float*)d_in[1];
    const float* g_b    = (const float*)d_in[2];
    const float* th_w   = (const float*)d_in[3];
    const float* th_b   = (const float*)d_in[4];
    const float* ph_w   = (const float*)d_in[5];
    const float* ph_b   = (const float*)d_in[6];
    const float* W_w    = (const float*)d_in[7];
    const float* W_b    = (const float*)d_in[8];
    const float* gamma  = (const float*)d_in[9];
    const float* beta   = (const float*)d_in[10];
    const float* mean   = (const float*)d_in[11];
    const float* var    = (const float*)d_in[12];
    float* z = (float*)d_out;

    pool_kernel<<<8192, 256>>>(x);
    dim3 pg(NTOK / 32, 13);
    proj_kernel<<<pg, 256>>>(g_w, g_b, th_w, th_b, ph_w, ph_b,
                             W_w, W_b, gamma, beta, mean, var);
    attn_kernel<<<NTOK, 256>>>();
    residual_kernel<<<(Bn * Cn * Sn * (REGION / 4)) / 256, 256>>>(x, z);
}